// round 13
// baseline (speedup 1.0000x reference)
#include <cuda_runtime.h>

#define NS 16
#define NZ 1000
#define NX 1000

#define DT_F    0.001f
#define HDT_F   0.0005f
#define INV_H_F 0.1f

#define AXW    999
#define AZW    998
#define AXROWS 998
#define AZROWS 999

#define TZ 8
#define TILEW 128

__device__ __forceinline__ int clampi(int v, int lo, int hi)
{
    return min(max(v, lo), hi);
}

__device__ __forceinline__ float4 ldg4_guard(const float* __restrict__ g, int f0, int tot)
{
    if (f0 >= 0 && f0 + 3 < tot)
        return *(const float4*)(g + f0);
    float t[4];
    #pragma unroll
    for (int k = 0; k < 4; k++) {
        const int fi = f0 + k;
        t[k] = (fi >= 0 && fi < tot) ? g[fi] : 0.f;
    }
    return make_float4(t[0], t[1], t[2], t[3]);
}

// Warp-cooperative aligned window load (coeff arrays). w[0..7] = flat elements
// [A0+4*lane .. A0+4*lane+7], A0 = F-(F&3). Returns d = F&3. All lanes must run.
__device__ __forceinline__ int warp_window(const float* __restrict__ g, int F, int tot,
                                           int lane, float w[8])
{
    const int d  = F & 3;
    const int A0 = F - d;
    float4 v = ldg4_guard(g, A0 + 4 * lane, tot);
    float4 vn;
    vn.x = __shfl_down_sync(0xffffffffu, v.x, 1);
    vn.y = __shfl_down_sync(0xffffffffu, v.y, 1);
    vn.z = __shfl_down_sync(0xffffffffu, v.z, 1);
    vn.w = __shfl_down_sync(0xffffffffu, v.w, 1);
    if (lane == 31) vn = ldg4_guard(g, A0 + 128, tot);
    w[0] = v.x;  w[1] = v.y;  w[2] = v.z;  w[3] = v.w;
    w[4] = vn.x; w[5] = vn.y; w[6] = vn.z; w[7] = vn.w;
    return d;
}

__device__ __forceinline__ void extract4(const float w[8], int d, float o[4])
{
    switch (d) {
        case 0:  o[0]=w[0]; o[1]=w[1]; o[2]=w[2]; o[3]=w[3]; break;
        case 1:  o[0]=w[1]; o[1]=w[2]; o[2]=w[3]; o[3]=w[4]; break;
        case 2:  o[0]=w[2]; o[1]=w[3]; o[2]=w[4]; o[3]=w[5]; break;
        default: o[0]=w[3]; o[1]=w[4]; o[2]=w[5]; o[3]=w[6]; break;
    }
}

// Warp-cooperative aligned row store with exact coverage (validated R11/R12).
__device__ __forceinline__ void warp_store_row(
    float* __restrict__ g, int F, int jcol0, int jmax, const float vals[4], int lane)
{
    const int d = F & 3;
    const float up1 = __shfl_up_sync(0xffffffffu, vals[1], 1);
    const float up2 = __shfl_up_sync(0xffffffffu, vals[2], 1);
    const float up3 = __shfl_up_sync(0xffffffffu, vals[3], 1);
    float4 sv;
    switch (d) {
        case 0:  sv = make_float4(vals[0], vals[1], vals[2], vals[3]); break;
        case 1:  sv = make_float4(up3, vals[0], vals[1], vals[2]); break;
        case 2:  sv = make_float4(up2, up3, vals[0], vals[1]); break;
        default: sv = make_float4(up1, up2, up3, vals[0]); break;
    }
    const int j0 = jcol0 + 4 * lane - d;
    const bool vecok = (d == 0 || lane >= 1) && (j0 >= 0) && (j0 + 3 <= jmax);
    const unsigned bal = __ballot_sync(0xffffffffu, vecok);
    if (vecok) __stcs((float4*)(g + (F - d) + 4 * lane), sv);

    const bool next_ok = (lane < 31) && ((bal >> (lane + 1)) & 1u);
    #pragma unroll
    for (int c = 0; c < 4; c++) {
        const bool covered = (d == 0) ? vecok : ((c < 4 - d) ? vecok : next_ok);
        if (!covered) {
            const int j = jcol0 + 4 * lane + c;
            if (j >= 0 && j <= jmax) __stcs(g + F + 4 * lane + c, vals[c]);
        }
    }
}

// Scalar P at one point (halo only)
__device__ __forceinline__ float compute_p_point(
    const float* __restrict__ Px, const float* __restrict__ Pz,
    const float* __restrict__ Ax, const float* __restrict__ Az,
    const float* __restrict__ src, const float* __restrict__ m2dt,
    const float* __restrict__ sigx, const float* __restrict__ sigz,
    int sOffP, int sOffAx, int sOffAz, int z, int x)
{
    float ax_x = 0.f, az_z = 0.f;
    if (z >= 1 && z <= NZ - 2 && x >= 1 && x <= NX - 2) {
        const float* axr = Ax + sOffAx + (z - 1) * AXW;
        ax_x = (__ldcs(axr + x) - __ldcs(axr + x - 1)) * INV_H_F;
        const float* azp = Az + sOffAz + (x - 1);
        az_z = (__ldcs(azp + z * AZW) - __ldcs(azp + (z - 1) * AZW)) * INV_H_F;
    }
    const int g2 = z * NX + x;
    const int g3 = sOffP + g2;
    const float sx = sigx[g2] * HDT_F;
    const float sz = sigz[g2] * HDT_F;
    const float m  = m2dt[g2];
    const float pxn = __fdividef(fmaf(m, ax_x, (1.f - sx) * __ldcs(Px + g3)), 1.f + sx);
    const float pzn = __fdividef(fmaf(m, az_z, (1.f - sz) * __ldcs(Pz + g3)), 1.f + sz);
    return pxn + pzn + __ldcs(src + g3) * DT_F;
}

__global__ __launch_bounds__(256, 5)
void pml_step_kernel(
    const float* __restrict__ Px,   const float* __restrict__ Pz,
    const float* __restrict__ Ax,   const float* __restrict__ Az,
    const float* __restrict__ src,
    const float* __restrict__ m2dt,
    const float* __restrict__ sigx, const float* __restrict__ sxh,
    const float* __restrict__ sigz, const float* __restrict__ szh,
    float* __restrict__ oPx, float* __restrict__ oPz,
    float* __restrict__ oAx, float* __restrict__ oAz,
    float* __restrict__ oP)
{
    __shared__ float sP[TZ + 1][TILEW + 4];

    const int s  = blockIdx.z;
    const int z0 = blockIdx.y * TZ;
    const int x0 = blockIdx.x * TILEW;
    const int tx = threadIdx.x;
    const int ty = threadIdx.y;
    const int tid = ty * 32 + tx;
    const int x  = x0 + 4 * tx;
    const int z  = z0 + ty;

    const int sOffP  = s * (NZ * NX);
    const int sOffAx = s * (AXROWS * AXW);
    const int sOffAz = s * (AZROWS * AZW);

    const bool xact = (x < NX);
    const bool zin  = (z >= 1) && (z <= NZ - 2);

    // Carry registers for phase 2
    float axk[5];   // Ax[z-1][x-1 .. x+3] (clamped cols)
    float azk[4];   // Az[z  ][x-1 .. x+2] (clamped cols/row)
    float pReg[4] = {0.f, 0.f, 0.f, 0.f};

    const int g2 = z * NX + x;
    const int g3 = sOffP + g2;

    // ---- Phase 1: branch-free clamped loads + masked compute ----
    if (xact) {
        const float4 pxv = __ldcs((const float4*)(Px + g3));
        const float4 pzv = __ldcs((const float4*)(Pz + g3));
        const float4 srv = __ldcs((const float4*)(src + g3));
        const float4 mv  = *(const float4*)(m2dt + g2);
        const float4 sxv = *(const float4*)(sigx + g2);
        const float4 szv = *(const float4*)(sigz + g2);

        // Clamped row bases (always valid addresses)
        const float* axr  = Ax + sOffAx + clampi(z - 1, 0, AXROWS - 1) * AXW;
        const float* az0r = Az + sOffAz + clampi(z - 1, 0, AZROWS - 1) * AZW;
        const float* az1r = Az + sOffAz + clampi(z,     0, AZROWS - 1) * AZW;

        float azlo[4];
        #pragma unroll
        for (int c = 0; c < 5; c++)
            axk[c] = __ldcs(axr + clampi(x - 1 + c, 0, AXW - 1));
        #pragma unroll
        for (int c = 0; c < 4; c++) {
            const int col = clampi(x - 1 + c, 0, AZW - 1);
            azlo[c] = __ldcs(az0r + col);
            azk[c]  = __ldcs(az1r + col);
        }

        const float px_in[4] = {pxv.x, pxv.y, pxv.z, pxv.w};
        const float pz_in[4] = {pzv.x, pzv.y, pzv.z, pzv.w};
        const float sr_in[4] = {srv.x, srv.y, srv.z, srv.w};
        const float m_in[4]  = {mv.x, mv.y, mv.z, mv.w};
        const float sx_in[4] = {sxv.x, sxv.y, sxv.z, sxv.w};
        const float sz_in[4] = {szv.x, szv.y, szv.z, szv.w};

        float pxn[4], pzn[4];
        #pragma unroll
        for (int c = 0; c < 4; c++) {
            const int xi = x + c;
            const bool msk = zin && (xi >= 1) && (xi <= NX - 2);
            const float ax_x = msk ? (axk[c + 1] - axk[c]) * INV_H_F : 0.f;
            const float az_z = msk ? (azk[c] - azlo[c]) * INV_H_F : 0.f;
            const float sx = sx_in[c] * HDT_F;
            const float sz = sz_in[c] * HDT_F;
            pxn[c] = __fdividef(fmaf(m_in[c], ax_x, (1.f - sx) * px_in[c]), 1.f + sx);
            pzn[c] = __fdividef(fmaf(m_in[c], az_z, (1.f - sz) * pz_in[c]), 1.f + sz);
            pReg[c] = pxn[c] + pzn[c] + sr_in[c] * DT_F;
        }

        __stcs((float4*)(oPx + g3), make_float4(pxn[0], pxn[1], pxn[2], pxn[3]));
        __stcs((float4*)(oPz + g3), make_float4(pzn[0], pzn[1], pzn[2], pzn[3]));
        __stcs((float4*)(oP  + g3), make_float4(pReg[0], pReg[1], pReg[2], pReg[3]));
        *(float4*)&sP[ty][4 * tx] = make_float4(pReg[0], pReg[1], pReg[2], pReg[3]);
    } else {
        #pragma unroll
        for (int c = 0; c < 5; c++) axk[c] = 0.f;
        #pragma unroll
        for (int c = 0; c < 4; c++) azk[c] = 0.f;
    }

    // ---- Halo P: bottom row + x-halo column ----
    if (tid < TILEW) {
        const int hz = z0 + TZ;
        const int hx = x0 + tid;
        if (hz < NZ && hx < NX)
            sP[TZ][tid] = compute_p_point(Px, Pz, Ax, Az, src, m2dt, sigx, sigz,
                                          sOffP, sOffAx, sOffAz, hz, hx);
    } else if (tid < TILEW + TZ) {
        const int r  = tid - TILEW;
        const int hx = x0 + TILEW;
        if (hx < NX)
            sP[r][TILEW] = compute_p_point(Px, Pz, Ax, Az, src, m2dt, sigx, sigz,
                                           sOffP, sOffAx, sOffAz, z0 + r, hx);
    }

    __syncthreads();

    // ---- Phase 2a: Ax_n row i = z-1 (warp-uniform; OOB columns masked in store) ----
    if (zin) {
        float wS[8], sxw[4];
        const int dS = warp_window(sxh, (z - 1) * AXW + x0, AXROWS * AXW, tx, wS);
        extract4(wS, dS, sxw);                    // sxh[z-1][x .. x+3]

        float pe = __shfl_down_sync(0xffffffffu, pReg[0], 1);   // P[z][x+4]
        if (tx == 31) pe = sP[ty][TILEW];

        float vals[4];
        #pragma unroll
        for (int c = 0; c < 4; c++) {
            const float pnext = (c < 3) ? pReg[c + 1] : pe;
            const float dfx = (pnext - pReg[c]) * INV_H_F;
            const float sv  = sxw[c] * HDT_F;
            vals[c] = __fdividef(fmaf(DT_F, dfx, (1.f - sv) * axk[c + 1]), 1.f + sv);
        }
        warp_store_row(oAx, sOffAx + (z - 1) * AXW + x0, x0, AXW - 1, vals, tx);
    }

    // ---- Phase 2b: Az_n row i = z (warp-uniform) ----
    if (z <= NZ - 2) {
        float wS[8], szw[4];
        const int dS = warp_window(szh, z * AZW + x0 - 1, AZROWS * AZW, tx, wS);
        extract4(wS, dS, szw);                    // szh[z][x-1 .. x+2]

        const float4 pb = *(const float4*)&sP[ty + 1][4 * tx];
        const float pbv[4] = {pb.x, pb.y, pb.z, pb.w};

        float vals[4];
        #pragma unroll
        for (int c = 0; c < 4; c++) {
            const float dfz = (pbv[c] - pReg[c]) * INV_H_F;
            const float sv  = szw[c] * HDT_F;
            vals[c] = __fdividef(fmaf(DT_F, dfz, (1.f - sv) * azk[c]), 1.f + sv);
        }
        warp_store_row(oAz, sOffAz + z * AZW + x0 - 1, x0 - 1, AZW - 1, vals, tx);
    }
}

extern "C" void kernel_launch(void* const* d_in, const int* in_sizes, int n_in,
                              void* d_out, int out_size)
{
    const float* Px   = (const float*)d_in[0];
    const float* Pz   = (const float*)d_in[1];
    const float* Ax   = (const float*)d_in[2];
    const float* Az   = (const float*)d_in[3];
    const float* src  = (const float*)d_in[4];
    const float* m2dt = (const float*)d_in[5];
    const float* sigx = (const float*)d_in[6];
    const float* sxh  = (const float*)d_in[7];
    const float* sigz = (const float*)d_in[8];
    const float* szh  = (const float*)d_in[9];

    float* out = (float*)d_out;
    const long long NP  = (long long)NS * NZ * NX;
    const long long NAX = (long long)NS * AXROWS * AXW;
    const long long NAZ = (long long)NS * AZROWS * AZW;

    float* oPx = out;
    float* oPz = oPx + NP;
    float* oAx = oPz + NP;
    float* oAz = oAx + NAX;
    float* oP  = oAz + NAZ;

    dim3 block(32, TZ, 1);
    dim3 grid((NX + TILEW - 1) / TILEW, NZ / TZ, NS);

    pml_step_kernel<<<grid, block>>>(Px, Pz, Ax, Az, src,
                                     m2dt, sigx, sxh, sigz, szh,
                                     oPx, oPz, oAx, oAz, oP);
}

// round 14
// speedup vs baseline: 1.0994x; 1.0994x over previous
#include <cuda_runtime.h>

#define NS 16
#define NZ 1000
#define NX 1000

#define DT_F    0.001f
#define HDT_F   0.0005f
#define INV_H_F 0.1f

#define AXW    999
#define AZW    998
#define AXROWS 998
#define AZROWS 999

#define XT 31            // owned output columns per warp-tile (warp spans 32)
#define ZT 8             // owned z rows per warp-tile (computes 9 P rows)
#define NXT 33           // ceil(1000/31)
#define NZT 125          // 1000/8

__global__ __launch_bounds__(256)
void pml_step_kernel(
    const float* __restrict__ Px,   const float* __restrict__ Pz,
    const float* __restrict__ Ax,   const float* __restrict__ Az,
    const float* __restrict__ src,
    const float* __restrict__ m2dt,
    const float* __restrict__ sigx, const float* __restrict__ sxh,
    const float* __restrict__ sigz, const float* __restrict__ szh,
    float* __restrict__ oPx, float* __restrict__ oPz,
    float* __restrict__ oAx, float* __restrict__ oAz,
    float* __restrict__ oP)
{
    const int lane = threadIdx.x;                    // 0..31
    const int zs   = blockIdx.y * 8 + threadIdx.y;   // 0..1999 (= 125 z-tiles x 16 shots)
    const int zt   = zs % NZT;
    const int s    = zs / NZT;
    const int x0   = blockIdx.x * XT;
    const int x    = x0 + lane;
    const int zb   = zt * ZT;

    const int sOffP  = s * (NZ * NX);
    const int sOffAx = s * (AXROWS * AXW);
    const int sOffAz = s * (AZROWS * AZW);

    const bool xP  = (x < NX);                       // P-grid output valid
    const bool xin = (x >= 1) && (x <= NX - 2);      // derivative interior
    const int  xc  = min(x, NX - 1);                 // clamped P-grid column
    const int  xA  = min(max(x - 1, 0), AXW - 1);    // Ax load column (= x-1)
    const int  xZ  = min(max(x - 1, 0), AZW - 1);    // Az load column (= x-1)
    const int  x31 = min(x0 + XT, AXW - 1);          // lane31 extra Ax column (= its x)
    const int  xS  = min(x, AXW - 1);                // sxh column (= x)

    // Prime carries: Az row zb-1 (garbage when zb==0 -> masked by zin)
    float azprev = Az[sOffAz + min(max(zb - 1, 0), AZROWS - 1) * AZW + xZ];
    float pPrev  = 0.f;

    #pragma unroll
    for (int zz = 0; zz <= ZT; zz++) {
        const int z = zb + zz;
        if (z < NZ) {                                 // warp-uniform
            const int g2 = z * NX + xc;
            const int g3 = sOffP + g2;
            const float pxv = Px[g3];
            const float pzv = Pz[g3];
            const float srv = src[g3];
            const float m2  = m2dt[g2];
            const float sgx = sigx[g2];
            const float sgz = sigz[g2];

            const int zA = min(max(z - 1, 0), AXROWS - 1);
            const float axv = Ax[sOffAx + zA * AXW + xA];       // Ax[z-1][x-1]
            float axn = __shfl_down_sync(0xffffffffu, axv, 1);  // Ax[z-1][x]
            if (lane == 31) axn = Ax[sOffAx + zA * AXW + x31];

            const int zZ = min(z, AZROWS - 1);
            const float azv = Az[sOffAz + zZ * AZW + xZ];       // Az[z][x-1]

            const bool zin = (z >= 1) && (z <= NZ - 2);
            const bool msk = zin && xin;
            const float ax_x = msk ? (axn - axv) * INV_H_F : 0.f;
            const float az_z = msk ? (azv - azprev) * INV_H_F : 0.f;

            const float sx  = sgx * HDT_F;
            const float sz  = sgz * HDT_F;
            const float pxn = __fdividef(fmaf(m2, ax_x, (1.f - sx) * pxv), 1.f + sx);
            const float pzn = __fdividef(fmaf(m2, az_z, (1.f - sz) * pzv), 1.f + sz);
            const float p   = pxn + pzn + srv * DT_F;

            if (zz < ZT && xP) {                      // owned P rows only
                __stcs(oPx + g3, pxn);
                __stcs(oPz + g3, pzn);
                __stcs(oP  + g3, p);
            }

            if (zz >= 1) {                            // phase 2 for row i = z-1
                const int i = z - 1;
                const float pr = __shfl_down_sync(0xffffffffu, p, 1);  // P[z][x+1]

                // Ax_n(i, j=x): P_x = (P[z][x+1]-P[z][x])/h, old Ax = axn
                const float sxv = sxh[min(i, AXROWS - 1) * AXW + xS] * HDT_F;
                const float vAx = __fdividef(
                    fmaf(DT_F, (pr - p) * INV_H_F, (1.f - sxv) * axn), 1.f + sxv);
                if (lane < 31 && x <= AXW - 1 && i <= AXROWS - 1)
                    __stcs(oAx + sOffAx + i * AXW + x, vAx);

                // Az_n(i, j=x-1): P_z = (P[z][x]-P[z-1][x])/h, old Az = azprev (= Az[i][x-1])
                const float szv = szh[min(i, AZROWS - 1) * AZW + xZ] * HDT_F;
                const float vAz = __fdividef(
                    fmaf(DT_F, (p - pPrev) * INV_H_F, (1.f - szv) * azprev), 1.f + szv);
                if (xin && i <= AZROWS - 1)
                    __stcs(oAz + sOffAz + i * AZW + (x - 1), vAz);
            }

            pPrev  = p;
            azprev = azv;
        }
    }
}

extern "C" void kernel_launch(void* const* d_in, const int* in_sizes, int n_in,
                              void* d_out, int out_size)
{
    const float* Px   = (const float*)d_in[0];
    const float* Pz   = (const float*)d_in[1];
    const float* Ax   = (const float*)d_in[2];
    const float* Az   = (const float*)d_in[3];
    const float* src  = (const float*)d_in[4];
    const float* m2dt = (const float*)d_in[5];
    const float* sigx = (const float*)d_in[6];
    const float* sxh  = (const float*)d_in[7];
    const float* sigz = (const float*)d_in[8];
    const float* szh  = (const float*)d_in[9];

    float* out = (float*)d_out;
    const long long NP  = (long long)NS * NZ * NX;
    const long long NAX = (long long)NS * AXROWS * AXW;
    const long long NAZ = (long long)NS * AZROWS * AZW;

    float* oPx = out;
    float* oPz = oPx + NP;
    float* oAx = oPz + NP;
    float* oAz = oAx + NAX;
    float* oP  = oAz + NAZ;

    dim3 block(32, 8, 1);
    dim3 grid(NXT, (NZT * NS) / 8, 1);   // 33 x-tiles, 250 blocks of 8 z/s-tiles

    pml_step_kernel<<<grid, block>>>(Px, Pz, Ax, Az, src,
                                     m2dt, sigx, sxh, sigz, szh,
                                     oPx, oPz, oAx, oAz, oP);
}